// round 5
// baseline (speedup 1.0000x reference)
#include <cuda_runtime.h>
#include <mma.h>

using namespace nvcuda;

#define N_NODES 50000
#define N_EDGES 800000
#define DIM     128
#define LD      132            // padded smem leading dim (floats)
#define BN_EPS  0.001f

// ---- scratch (allocation-free rule: __device__ globals) ----
__device__ __align__(256) float g_H[N_NODES * DIM];
__device__ __align__(256) float g_sums[N_NODES * DIM];
__device__ __align__(256) float g_counts[N_NODES];

// vectorized global float4 reduction (sm_90+; one RED.128 instead of 4 REDs)
__device__ __forceinline__ void red_add_v4(float* ptr, float a, float b,
                                           float c, float d) {
    asm volatile("red.global.add.v4.f32 [%0], {%1, %2, %3, %4};"
                 :: "l"(ptr), "f"(a), "f"(b), "f"(c), "f"(d)
                 : "memory");
}

// ---------------------------------------------------------------------------
// zero scratch
// ---------------------------------------------------------------------------
__global__ void zero_kernel() {
    int i = blockIdx.x * blockDim.x + threadIdx.x;
    if (i < N_NODES * DIM / 4)
        reinterpret_cast<float4*>(g_sums)[i] = make_float4(0.f, 0.f, 0.f, 0.f);
    if (i < N_NODES / 4)
        reinterpret_cast<float4*>(g_counts)[i] = make_float4(0.f, 0.f, 0.f, 0.f);
}

// ---------------------------------------------------------------------------
// node_hidden = node_features @ W_node + b_node   (tf32 wmma, 64-row tiles)
// smem: W (128 x LD) + tile (64 x LD)
// ---------------------------------------------------------------------------
__global__ void node_kernel(const float* __restrict__ X,
                            const float* __restrict__ W,
                            const float* __restrict__ b) {
    extern __shared__ float smem[];
    float* sW = smem;                 // 128*LD
    float* sE = smem + 128 * LD;      // 64*LD
    const int tid = threadIdx.x;
    const int wid = tid >> 5;

    // load W (tf32-converted)
    for (int idx = tid; idx < 128 * 32; idx += 256) {
        int r = idx >> 5, c = (idx & 31) << 2;
        float4 v = *reinterpret_cast<const float4*>(&W[r * DIM + c]);
        float* d = &sW[r * LD + c];
        d[0] = wmma::__float_to_tf32(v.x);
        d[1] = wmma::__float_to_tf32(v.y);
        d[2] = wmma::__float_to_tf32(v.z);
        d[3] = wmma::__float_to_tf32(v.w);
    }

    const int e0 = blockIdx.x * 64;
    for (int idx = tid; idx < 64 * 32; idx += 256) {
        int r = idx >> 5, c = (idx & 31) << 2;
        float4 v = (e0 + r < N_NODES)
                       ? *reinterpret_cast<const float4*>(&X[(size_t)(e0 + r) * DIM + c])
                       : make_float4(0.f, 0.f, 0.f, 0.f);
        float* d = &sE[r * LD + c];
        d[0] = wmma::__float_to_tf32(v.x);
        d[1] = wmma::__float_to_tf32(v.y);
        d[2] = wmma::__float_to_tf32(v.z);
        d[3] = wmma::__float_to_tf32(v.w);
    }
    __syncthreads();

    const int mt = wid & 3;    // 4 m-tiles of 16 rows
    const int nh = wid >> 2;   // 2 n-halves of 64 cols

    wmma::fragment<wmma::accumulator, 16, 16, 8, float> acc[4];
#pragma unroll
    for (int i = 0; i < 4; i++) wmma::fill_fragment(acc[i], 0.f);

#pragma unroll
    for (int k = 0; k < 16; k++) {
        wmma::fragment<wmma::matrix_a, 16, 16, 8, wmma::precision::tf32, wmma::row_major> a;
        wmma::load_matrix_sync(a, sE + mt * 16 * LD + k * 8, LD);
#pragma unroll
        for (int nf = 0; nf < 4; nf++) {
            wmma::fragment<wmma::matrix_b, 16, 16, 8, wmma::precision::tf32, wmma::row_major> bf;
            wmma::load_matrix_sync(bf, sW + k * 8 * LD + nh * 64 + nf * 16, LD);
            wmma::mma_sync(acc[nf], a, bf, acc[nf]);
        }
    }
    __syncthreads();
#pragma unroll
    for (int nf = 0; nf < 4; nf++)
        wmma::store_matrix_sync(sE + mt * 16 * LD + nh * 64 + nf * 16, acc[nf], LD,
                                wmma::mem_row_major);
    __syncthreads();

    for (int i = 0; i < 8; i++) {
        int idx4 = tid + i * 256;
        int r = idx4 >> 5, c = (idx4 & 31) << 2;
        int row = e0 + r;
        if (row < N_NODES) {
            float4 bv = *reinterpret_cast<const float4*>(&b[c]);
            float4 v;
            v.x = sE[r * LD + c + 0] + bv.x;
            v.y = sE[r * LD + c + 1] + bv.y;
            v.z = sE[r * LD + c + 2] + bv.z;
            v.w = sE[r * LD + c + 3] + bv.w;
            *reinterpret_cast<float4*>(&g_H[(size_t)row * DIM + c]) = v;
        }
    }
}

// ---------------------------------------------------------------------------
// fused edge kernel (persistent): gate/filt GEMMs + gather + scatter-add
// Double-buffered A tile: prefetch next tile to registers during MMA.
// smem: Wg (128xLD) + Wf (128xLD) + sA[2] (64xLD each)
// ---------------------------------------------------------------------------
__global__ void edge_kernel(const float* __restrict__ Ef,
                            const float* __restrict__ Wg, const float* __restrict__ bg,
                            const float* __restrict__ Wf, const float* __restrict__ bf,
                            const int* __restrict__ ei) {
    extern __shared__ float smem[];
    float* sWg = smem;                      // 128*LD
    float* sWf = smem + 128 * LD;           // 128*LD
    float* sA0 = smem + 2 * 128 * LD;       // 64*LD
    float* sA1 = sA0 + 64 * LD;             // 64*LD

    const int tid = threadIdx.x;
    const int wid = tid >> 5;

    // load both weight matrices once per (persistent) block
    for (int idx = tid; idx < 128 * 32; idx += 256) {
        int r = idx >> 5, c = (idx & 31) << 2;
        float4 vg = *reinterpret_cast<const float4*>(&Wg[r * DIM + c]);
        float4 vf = *reinterpret_cast<const float4*>(&Wf[r * DIM + c]);
        float* dg = &sWg[r * LD + c];
        float* df = &sWf[r * LD + c];
        dg[0] = wmma::__float_to_tf32(vg.x); dg[1] = wmma::__float_to_tf32(vg.y);
        dg[2] = wmma::__float_to_tf32(vg.z); dg[3] = wmma::__float_to_tf32(vg.w);
        df[0] = wmma::__float_to_tf32(vf.x); df[1] = wmma::__float_to_tf32(vf.y);
        df[2] = wmma::__float_to_tf32(vf.z); df[3] = wmma::__float_to_tf32(vf.w);
    }

    const int mt = wid & 3;
    const int nh = wid >> 2;
    const int n_tiles = N_EDGES / 64;   // 12500 exactly

    // fixed per-thread (r, c) mapping used by all tile-shaped loops:
    // element i covers idx4 = tid + i*256  ->  r = idx4>>5, c = (idx4&31)<<2
    const int ccol = (tid & 31) << 2;
    const float4 bg4 = *reinterpret_cast<const float4*>(&bg[ccol]);
    const float4 bf4 = *reinterpret_cast<const float4*>(&bf[ccol]);

    // ---- preload first assigned tile into buffer 0 ----
    int tile = blockIdx.x;
    if (tile < n_tiles) {
        const int e0 = tile * 64;
#pragma unroll
        for (int i = 0; i < 8; i++) {
            int idx4 = tid + i * 256;
            int r = idx4 >> 5, c = (idx4 & 31) << 2;
            float4 v = *reinterpret_cast<const float4*>(&Ef[(size_t)(e0 + r) * DIM + c]);
            float* d = &sA0[r * LD + c];
            d[0] = wmma::__float_to_tf32(v.x);
            d[1] = wmma::__float_to_tf32(v.y);
            d[2] = wmma::__float_to_tf32(v.z);
            d[3] = wmma::__float_to_tf32(v.w);
        }
    }
    __syncthreads();

    int buf = 0;
    for (; tile < n_tiles; tile += gridDim.x) {
        const int e0 = tile * 64;
        float* sE = buf ? sA1 : sA0;       // current A tile / staging buffer
        float* sN = buf ? sA0 : sA1;       // next A tile destination

        // ---- prefetch next tile into registers (overlaps MMA below) ----
        const int ntile = tile + gridDim.x;
        float4 pre[8];
        if (ntile < n_tiles) {
            const int ne0 = ntile * 64;
#pragma unroll
            for (int i = 0; i < 8; i++) {
                int idx4 = tid + i * 256;
                int r = idx4 >> 5, c = (idx4 & 31) << 2;
                pre[i] = *reinterpret_cast<const float4*>(&Ef[(size_t)(ne0 + r) * DIM + c]);
            }
        }

        // ---- dual GEMM on current tile ----
        wmma::fragment<wmma::accumulator, 16, 16, 8, float> accg[4], accf[4];
#pragma unroll
        for (int i = 0; i < 4; i++) {
            wmma::fill_fragment(accg[i], 0.f);
            wmma::fill_fragment(accf[i], 0.f);
        }

#pragma unroll
        for (int k = 0; k < 16; k++) {
            wmma::fragment<wmma::matrix_a, 16, 16, 8, wmma::precision::tf32, wmma::row_major> a;
            wmma::load_matrix_sync(a, sE + mt * 16 * LD + k * 8, LD);
#pragma unroll
            for (int nf = 0; nf < 4; nf++) {
                wmma::fragment<wmma::matrix_b, 16, 16, 8, wmma::precision::tf32, wmma::row_major> bb;
                wmma::load_matrix_sync(bb, sWg + k * 8 * LD + nh * 64 + nf * 16, LD);
                wmma::mma_sync(accg[nf], a, bb, accg[nf]);
                wmma::load_matrix_sync(bb, sWf + k * 8 * LD + nh * 64 + nf * 16, LD);
                wmma::mma_sync(accf[nf], a, bb, accf[nf]);
            }
        }
        __syncthreads();   // all warps done reading sE as A-tile

        // ---- commit prefetched tile into the other buffer (no reader yet) ----
        if (ntile < n_tiles) {
#pragma unroll
            for (int i = 0; i < 8; i++) {
                int idx4 = tid + i * 256;
                int r = idx4 >> 5, c = (idx4 & 31) << 2;
                float* d = &sN[r * LD + c];
                d[0] = wmma::__float_to_tf32(pre[i].x);
                d[1] = wmma::__float_to_tf32(pre[i].y);
                d[2] = wmma::__float_to_tf32(pre[i].z);
                d[3] = wmma::__float_to_tf32(pre[i].w);
            }
        }

        // ---- stage F into sE, stash to registers ----
#pragma unroll
        for (int nf = 0; nf < 4; nf++)
            wmma::store_matrix_sync(sE + mt * 16 * LD + nh * 64 + nf * 16, accf[nf], LD,
                                    wmma::mem_row_major);
        __syncthreads();
        float fst[32];
#pragma unroll
        for (int i = 0; i < 8; i++) {
            int idx4 = tid + i * 256;
            int r = idx4 >> 5, c = (idx4 & 31) << 2;
            float4 v = *reinterpret_cast<float4*>(&sE[r * LD + c]);
            fst[i * 4 + 0] = v.x; fst[i * 4 + 1] = v.y;
            fst[i * 4 + 2] = v.z; fst[i * 4 + 3] = v.w;
        }
        __syncthreads();
        // ---- stage G into sE ----
#pragma unroll
        for (int nf = 0; nf < 4; nf++)
            wmma::store_matrix_sync(sE + mt * 16 * LD + nh * 64 + nf * 16, accg[nf], LD,
                                    wmma::mem_row_major);
        __syncthreads();

        // ---- epilogue: sigmoid(G+bg) * (F+bf) * H[dst] -> RED.v4 sums[src] ----
#pragma unroll
        for (int i = 0; i < 8; i++) {
            int idx4 = tid + i * 256;
            int r = idx4 >> 5, c = (idx4 & 31) << 2;
            int e = e0 + r;
            int src = ei[2 * e + 0];
            int dst = ei[2 * e + 1];
            float4 g4 = *reinterpret_cast<float4*>(&sE[r * LD + c]);
            float4 h4 = *reinterpret_cast<const float4*>(&g_H[(size_t)dst * DIM + c]);

            float gate;
            float m0, m1, m2, m3;
            gate = 1.f / (1.f + __expf(-(g4.x + bg4.x)));
            m0 = gate * (fst[i * 4 + 0] + bf4.x) * h4.x;
            gate = 1.f / (1.f + __expf(-(g4.y + bg4.y)));
            m1 = gate * (fst[i * 4 + 1] + bf4.y) * h4.y;
            gate = 1.f / (1.f + __expf(-(g4.z + bg4.z)));
            m2 = gate * (fst[i * 4 + 2] + bf4.z) * h4.z;
            gate = 1.f / (1.f + __expf(-(g4.w + bg4.w)));
            m3 = gate * (fst[i * 4 + 3] + bf4.w) * h4.w;
            red_add_v4(&g_sums[(size_t)src * DIM + c], m0, m1, m2, m3);
        }
        if (tid < 64) {
            int e = e0 + tid;
            atomicAdd(&g_counts[ei[2 * e]], 1.0f);
        }

        buf ^= 1;
        __syncthreads();   // epilogue reads of sE done; sN visible for next MMA
    }
}

// ---------------------------------------------------------------------------
// finalize: out = relu(BN(H + sums/count))
// ---------------------------------------------------------------------------
__global__ void final_kernel(const float* __restrict__ gamma,
                             const float* __restrict__ beta,
                             const float* __restrict__ mean,
                             const float* __restrict__ var,
                             float* __restrict__ out) {
    int idx4 = blockIdx.x * blockDim.x + threadIdx.x;
    if (idx4 >= N_NODES * DIM / 4) return;
    int r = idx4 >> 5, c = (idx4 & 31) << 2;
    float cnt = g_counts[r];
    float inv = cnt > 0.f ? 1.f / cnt : 0.f;
    float4 h = reinterpret_cast<const float4*>(g_H)[idx4];
    float4 s = reinterpret_cast<const float4*>(g_sums)[idx4];
    float4 m4 = *reinterpret_cast<const float4*>(&mean[c]);
    float4 v4 = *reinterpret_cast<const float4*>(&var[c]);
    float4 g4 = *reinterpret_cast<const float4*>(&gamma[c]);
    float4 b4 = *reinterpret_cast<const float4*>(&beta[c]);

    float4 o;
    o.x = (h.x + s.x * inv - m4.x) * rsqrtf(v4.x + BN_EPS) * g4.x + b4.x;
    o.y = (h.y + s.y * inv - m4.y) * rsqrtf(v4.y + BN_EPS) * g4.y + b4.y;
    o.z = (h.z + s.z * inv - m4.z) * rsqrtf(v4.z + BN_EPS) * g4.z + b4.z;
    o.w = (h.w + s.w * inv - m4.w) * rsqrtf(v4.w + BN_EPS) * g4.w + b4.w;
    o.x = fmaxf(o.x, 0.f); o.y = fmaxf(o.y, 0.f);
    o.z = fmaxf(o.z, 0.f); o.w = fmaxf(o.w, 0.f);
    reinterpret_cast<float4*>(out)[idx4] = o;
}

// ---------------------------------------------------------------------------
extern "C" void kernel_launch(void* const* d_in, const int* in_sizes, int n_in,
                              void* d_out, int out_size) {
    const float* node_features = (const float*)d_in[0];
    const float* edge_features = (const float*)d_in[1];
    const float* W_node = (const float*)d_in[2];
    const float* b_node = (const float*)d_in[3];
    const float* W_gate = (const float*)d_in[4];
    const float* b_gate = (const float*)d_in[5];
    const float* W_filt = (const float*)d_in[6];
    const float* b_filt = (const float*)d_in[7];
    const float* bn_gamma = (const float*)d_in[8];
    const float* bn_beta = (const float*)d_in[9];
    const float* bn_mean = (const float*)d_in[10];
    const float* bn_var = (const float*)d_in[11];
    const int*   edge_indices = (const int*)d_in[12];

    const int NODE_SMEM = (128 * LD + 64 * LD) * 4;              // 101376 B
    const int EDGE_SMEM = (2 * 128 * LD + 2 * 64 * LD) * 4;      // 202752 B
    cudaFuncSetAttribute(node_kernel, cudaFuncAttributeMaxDynamicSharedMemorySize, NODE_SMEM);
    cudaFuncSetAttribute(edge_kernel, cudaFuncAttributeMaxDynamicSharedMemorySize, EDGE_SMEM);

    zero_kernel<<<(N_NODES * DIM / 4 + 255) / 256, 256>>>();
    node_kernel<<<(N_NODES + 63) / 64, 256, NODE_SMEM>>>(node_features, W_node, b_node);
    edge_kernel<<<148, 256, EDGE_SMEM>>>(edge_features, W_gate, b_gate,
                                         W_filt, b_filt, edge_indices);
    final_kernel<<<(N_NODES * DIM / 4 + 255) / 256, 256>>>(bn_gamma, bn_beta,
                                                           bn_mean, bn_var,
                                                           (float*)d_out);
}

// round 7
// speedup vs baseline: 2.5658x; 2.5658x over previous
#include <cuda_runtime.h>
#include <cuda_fp16.h>
#include <mma.h>

using namespace nvcuda;

#define N_NODES 50000
#define N_EDGES 800000
#define DIM     128
#define LD      132            // fp32 stage leading dim (floats)
#define LDH     136            // fp16 tile leading dim (halfs; 16B row pad)
#define BN_EPS  0.001f

// ---- scratch (allocation-free rule: __device__ globals) ----
__device__ __align__(256) float g_H[N_NODES * DIM];
__device__ __align__(256) float g_sums[N_NODES * DIM];
__device__ __align__(256) float g_counts[N_NODES];

// vectorized global float4 reduction (one RED.128 instead of 4 REDs)
__device__ __forceinline__ void red_add_v4(float* ptr, float a, float b,
                                           float c, float d) {
    asm volatile("red.global.add.v4.f32 [%0], {%1, %2, %3, %4};"
                 :: "l"(ptr), "f"(a), "f"(b), "f"(c), "f"(d)
                 : "memory");
}

// sigmoid via single MUFU.TANH: sigmoid(x) = 0.5*tanh(x/2) + 0.5
__device__ __forceinline__ float fast_sigmoid(float x) {
    float t;
    asm("tanh.approx.f32 %0, %1;" : "=f"(t) : "f"(0.5f * x));
    return fmaf(0.5f, t, 0.5f);
}

// convert float4 -> 4 halfs at smem destination
__device__ __forceinline__ void st_half4(__half* d, float4 v) {
    __half2* d2 = reinterpret_cast<__half2*>(d);
    d2[0] = __floats2half2_rn(v.x, v.y);
    d2[1] = __floats2half2_rn(v.z, v.w);
}

// ---------------------------------------------------------------------------
// zero scratch
// ---------------------------------------------------------------------------
__global__ void zero_kernel() {
    int i = blockIdx.x * blockDim.x + threadIdx.x;
    if (i < N_NODES * DIM / 4)
        reinterpret_cast<float4*>(g_sums)[i] = make_float4(0.f, 0.f, 0.f, 0.f);
    if (i < N_NODES / 4)
        reinterpret_cast<float4*>(g_counts)[i] = make_float4(0.f, 0.f, 0.f, 0.f);
}

// ---------------------------------------------------------------------------
// node_hidden = node_features @ W_node + b_node   (fp16 wmma m16n16k16)
// smem: W half(128xLDH) + E half(64xLDH) + stage float(64xLD)
// ---------------------------------------------------------------------------
__global__ void node_kernel(const float* __restrict__ X,
                            const float* __restrict__ W,
                            const float* __restrict__ b) {
    extern __shared__ char smem_raw[];
    __half* sW = reinterpret_cast<__half*>(smem_raw);                  // 128*LDH
    __half* sE = sW + 128 * LDH;                                       // 64*LDH
    float*  sS = reinterpret_cast<float*>(sE + 64 * LDH);              // 64*LD
    const int tid = threadIdx.x;
    const int wid = tid >> 5;

    for (int idx = tid; idx < 128 * 32; idx += 256) {
        int r = idx >> 5, c = (idx & 31) << 2;
        float4 v = *reinterpret_cast<const float4*>(&W[r * DIM + c]);
        st_half4(&sW[r * LDH + c], v);
    }

    const int e0 = blockIdx.x * 64;
    for (int idx = tid; idx < 64 * 32; idx += 256) {
        int r = idx >> 5, c = (idx & 31) << 2;
        float4 v = (e0 + r < N_NODES)
                       ? *reinterpret_cast<const float4*>(&X[(size_t)(e0 + r) * DIM + c])
                       : make_float4(0.f, 0.f, 0.f, 0.f);
        st_half4(&sE[r * LDH + c], v);
    }
    __syncthreads();

    const int mt = wid & 3;    // 4 m-tiles of 16 rows
    const int nh = wid >> 2;   // 2 n-halves of 64 cols

    wmma::fragment<wmma::accumulator, 16, 16, 16, float> acc[4];
#pragma unroll
    for (int i = 0; i < 4; i++) wmma::fill_fragment(acc[i], 0.f);

#pragma unroll
    for (int k = 0; k < 8; k++) {
        wmma::fragment<wmma::matrix_a, 16, 16, 16, __half, wmma::row_major> a;
        wmma::load_matrix_sync(a, sE + mt * 16 * LDH + k * 16, LDH);
#pragma unroll
        for (int nf = 0; nf < 4; nf++) {
            wmma::fragment<wmma::matrix_b, 16, 16, 16, __half, wmma::row_major> bf;
            wmma::load_matrix_sync(bf, sW + k * 16 * LDH + nh * 64 + nf * 16, LDH);
            wmma::mma_sync(acc[nf], a, bf, acc[nf]);
        }
    }
    __syncthreads();
#pragma unroll
    for (int nf = 0; nf < 4; nf++)
        wmma::store_matrix_sync(sS + mt * 16 * LD + nh * 64 + nf * 16, acc[nf], LD,
                                wmma::mem_row_major);
    __syncthreads();

    for (int i = 0; i < 8; i++) {
        int idx4 = tid + i * 256;
        int r = idx4 >> 5, c = (idx4 & 31) << 2;
        int row = e0 + r;
        if (row < N_NODES) {
            float4 bv = *reinterpret_cast<const float4*>(&b[c]);
            float4 v;
            v.x = sS[r * LD + c + 0] + bv.x;
            v.y = sS[r * LD + c + 1] + bv.y;
            v.z = sS[r * LD + c + 2] + bv.z;
            v.w = sS[r * LD + c + 3] + bv.w;
            *reinterpret_cast<float4*>(&g_H[(size_t)row * DIM + c]) = v;
        }
    }
}

// ---------------------------------------------------------------------------
// fused edge kernel (persistent): gate/filt fp16 GEMMs + gather + scatter-add
// smem: Wg half(128xLDH) + Wf half(128xLDH) + A half x2 (64xLDH) + stage f32(64xLD)
// ---------------------------------------------------------------------------
__global__ void edge_kernel(const float* __restrict__ Ef,
                            const float* __restrict__ Wg, const float* __restrict__ bg,
                            const float* __restrict__ Wf, const float* __restrict__ bf,
                            const int* __restrict__ ei) {
    extern __shared__ char smem_raw[];
    __half* sWg = reinterpret_cast<__half*>(smem_raw);     // 128*LDH
    __half* sWf = sWg + 128 * LDH;                         // 128*LDH
    __half* sA0 = sWf + 128 * LDH;                         // 64*LDH
    __half* sA1 = sA0 + 64 * LDH;                          // 64*LDH
    float*  sS  = reinterpret_cast<float*>(sA1 + 64 * LDH); // 64*LD fp32 stage

    const int tid = threadIdx.x;
    const int wid = tid >> 5;

    // load both weight matrices once per (persistent) block
    for (int idx = tid; idx < 128 * 32; idx += 256) {
        int r = idx >> 5, c = (idx & 31) << 2;
        float4 vg = *reinterpret_cast<const float4*>(&Wg[r * DIM + c]);
        float4 vf = *reinterpret_cast<const float4*>(&Wf[r * DIM + c]);
        st_half4(&sWg[r * LDH + c], vg);
        st_half4(&sWf[r * LDH + c], vf);
    }

    const int mt = wid & 3;
    const int nh = wid >> 2;
    const int n_tiles = N_EDGES / 64;   // 12500 exactly

    const int ccol = (tid & 31) << 2;
    const float4 bg4 = *reinterpret_cast<const float4*>(&bg[ccol]);
    const float4 bf4 = *reinterpret_cast<const float4*>(&bf[ccol]);

    // ---- preload first assigned tile into buffer 0 ----
    int tile = blockIdx.x;
    if (tile < n_tiles) {
        const int e0 = tile * 64;
#pragma unroll
        for (int i = 0; i < 8; i++) {
            int idx4 = tid + i * 256;
            int r = idx4 >> 5, c = (idx4 & 31) << 2;
            float4 v = *reinterpret_cast<const float4*>(&Ef[(size_t)(e0 + r) * DIM + c]);
            st_half4(&sA0[r * LDH + c], v);
        }
    }
    __syncthreads();

    int buf = 0;
    for (; tile < n_tiles; tile += gridDim.x) {
        const int e0 = tile * 64;
        __half* sE = buf ? sA1 : sA0;      // current A tile
        __half* sN = buf ? sA0 : sA1;      // next A tile destination

        // ---- prefetch next tile into registers (overlaps MMA below) ----
        const int ntile = tile + gridDim.x;
        float4 pre[8];
        if (ntile < n_tiles) {
            const int ne0 = ntile * 64;
#pragma unroll
            for (int i = 0; i < 8; i++) {
                int idx4 = tid + i * 256;
                int r = idx4 >> 5, c = (idx4 & 31) << 2;
                pre[i] = *reinterpret_cast<const float4*>(&Ef[(size_t)(ne0 + r) * DIM + c]);
            }
        }

        // ---- dual GEMM on current tile (fp16, k16) ----
        wmma::fragment<wmma::accumulator, 16, 16, 16, float> accg[4], accf[4];
#pragma unroll
        for (int i = 0; i < 4; i++) {
            wmma::fill_fragment(accg[i], 0.f);
            wmma::fill_fragment(accf[i], 0.f);
        }

#pragma unroll
        for (int k = 0; k < 8; k++) {
            wmma::fragment<wmma::matrix_a, 16, 16, 16, __half, wmma::row_major> a;
            wmma::load_matrix_sync(a, sE + mt * 16 * LDH + k * 16, LDH);
#pragma unroll
            for (int nf = 0; nf < 4; nf++) {
                wmma::fragment<wmma::matrix_b, 16, 16, 16, __half, wmma::row_major> bb;
                wmma::load_matrix_sync(bb, sWg + k * 16 * LDH + nh * 64 + nf * 16, LDH);
                wmma::mma_sync(accg[nf], a, bb, accg[nf]);
                wmma::load_matrix_sync(bb, sWf + k * 16 * LDH + nh * 64 + nf * 16, LDH);
                wmma::mma_sync(accf[nf], a, bb, accf[nf]);
            }
        }
        __syncthreads();   // all warps done reading sE as A-tile

        // ---- commit prefetched tile into the other buffer (no reader yet) ----
        if (ntile < n_tiles) {
#pragma unroll
            for (int i = 0; i < 8; i++) {
                int idx4 = tid + i * 256;
                int r = idx4 >> 5, c = (idx4 & 31) << 2;
                st_half4(&sN[r * LDH + c], pre[i]);
            }
        }

        // ---- stage F into sS, stash to registers ----
#pragma unroll
        for (int nf = 0; nf < 4; nf++)
            wmma::store_matrix_sync(sS + mt * 16 * LD + nh * 64 + nf * 16, accf[nf], LD,
                                    wmma::mem_row_major);
        __syncthreads();
        float fst[32];
#pragma unroll
        for (int i = 0; i < 8; i++) {
            int idx4 = tid + i * 256;
            int r = idx4 >> 5, c = (idx4 & 31) << 2;
            float4 v = *reinterpret_cast<float4*>(&sS[r * LD + c]);
            fst[i * 4 + 0] = v.x; fst[i * 4 + 1] = v.y;
            fst[i * 4 + 2] = v.z; fst[i * 4 + 3] = v.w;
        }
        __syncthreads();
        // ---- stage G into sS ----
#pragma unroll
        for (int nf = 0; nf < 4; nf++)
            wmma::store_matrix_sync(sS + mt * 16 * LD + nh * 64 + nf * 16, accg[nf], LD,
                                    wmma::mem_row_major);
        __syncthreads();

        // ---- epilogue: sigmoid(G+bg) * (F+bf) * H[dst] -> RED.v4 sums[src] ----
#pragma unroll
        for (int i = 0; i < 8; i++) {
            int idx4 = tid + i * 256;
            int r = idx4 >> 5, c = (idx4 & 31) << 2;
            int e = e0 + r;
            int src = ei[2 * e + 0];
            int dst = ei[2 * e + 1];
            float4 g4 = *reinterpret_cast<float4*>(&sS[r * LD + c]);
            float4 h4 = *reinterpret_cast<const float4*>(&g_H[(size_t)dst * DIM + c]);

            float m0, m1, m2, m3;
            m0 = fast_sigmoid(g4.x + bg4.x) * (fst[i * 4 + 0] + bf4.x) * h4.x;
            m1 = fast_sigmoid(g4.y + bg4.y) * (fst[i * 4 + 1] + bf4.y) * h4.y;
            m2 = fast_sigmoid(g4.z + bg4.z) * (fst[i * 4 + 2] + bf4.z) * h4.z;
            m3 = fast_sigmoid(g4.w + bg4.w) * (fst[i * 4 + 3] + bf4.w) * h4.w;
            red_add_v4(&g_sums[(size_t)src * DIM + c], m0, m1, m2, m3);
        }
        if (tid < 64) {
            int e = e0 + tid;
            atomicAdd(&g_counts[ei[2 * e]], 1.0f);
        }

        buf ^= 1;
        __syncthreads();   // epilogue reads of sS done; sN visible for next MMA
    }
}

// ---------------------------------------------------------------------------
// finalize: out = relu(BN(H + sums/count))
// ---------------------------------------------------------------------------
__global__ void final_kernel(const float* __restrict__ gamma,
                             const float* __restrict__ beta,
                             const float* __restrict__ mean,
                             const float* __restrict__ var,
                             float* __restrict__ out) {
    int idx4 = blockIdx.x * blockDim.x + threadIdx.x;
    if (idx4 >= N_NODES * DIM / 4) return;
    int r = idx4 >> 5, c = (idx4 & 31) << 2;
    float cnt = g_counts[r];
    float inv = cnt > 0.f ? 1.f / cnt : 0.f;
    float4 h = reinterpret_cast<const float4*>(g_H)[idx4];
    float4 s = reinterpret_cast<const float4*>(g_sums)[idx4];
    float4 m4 = *reinterpret_cast<const float4*>(&mean[c]);
    float4 v4 = *reinterpret_cast<const float4*>(&var[c]);
    float4 g4 = *reinterpret_cast<const float4*>(&gamma[c]);
    float4 b4 = *reinterpret_cast<const float4*>(&beta[c]);

    float4 o;
    o.x = (h.x + s.x * inv - m4.x) * rsqrtf(v4.x + BN_EPS) * g4.x + b4.x;
    o.y = (h.y + s.y * inv - m4.y) * rsqrtf(v4.y + BN_EPS) * g4.y + b4.y;
    o.z = (h.z + s.z * inv - m4.z) * rsqrtf(v4.z + BN_EPS) * g4.z + b4.z;
    o.w = (h.w + s.w * inv - m4.w) * rsqrtf(v4.w + BN_EPS) * g4.w + b4.w;
    o.x = fmaxf(o.x, 0.f); o.y = fmaxf(o.y, 0.f);
    o.z = fmaxf(o.z, 0.f); o.w = fmaxf(o.w, 0.f);
    reinterpret_cast<float4*>(out)[idx4] = o;
}

// ---------------------------------------------------------------------------
extern "C" void kernel_launch(void* const* d_in, const int* in_sizes, int n_in,
                              void* d_out, int out_size) {
    const float* node_features = (const float*)d_in[0];
    const float* edge_features = (const float*)d_in[1];
    const float* W_node = (const float*)d_in[2];
    const float* b_node = (const float*)d_in[3];
    const float* W_gate = (const float*)d_in[4];
    const float* b_gate = (const float*)d_in[5];
    const float* W_filt = (const float*)d_in[6];
    const float* b_filt = (const float*)d_in[7];
    const float* bn_gamma = (const float*)d_in[8];
    const float* bn_beta = (const float*)d_in[9];
    const float* bn_mean = (const float*)d_in[10];
    const float* bn_var = (const float*)d_in[11];
    const int*   edge_indices = (const int*)d_in[12];

    // node: W half + E half + stage f32
    const int NODE_SMEM = (128 * LDH + 64 * LDH) * 2 + 64 * LD * 4;      // 86016 B
    // edge: 2x W half + 2x A half + stage f32
    const int EDGE_SMEM = (2 * 128 * LDH + 2 * 64 * LDH) * 2 + 64 * LD * 4; // 138240 B
    cudaFuncSetAttribute(node_kernel, cudaFuncAttributeMaxDynamicSharedMemorySize, NODE_SMEM);
    cudaFuncSetAttribute(edge_kernel, cudaFuncAttributeMaxDynamicSharedMemorySize, EDGE_SMEM);

    zero_kernel<<<(N_NODES * DIM / 4 + 255) / 256, 256>>>();
    node_kernel<<<(N_NODES + 63) / 64, 256, NODE_SMEM>>>(node_features, W_node, b_node);
    edge_kernel<<<148, 256, EDGE_SMEM>>>(edge_features, W_gate, b_gate,
                                         W_filt, b_filt, edge_indices);
    final_kernel<<<(N_NODES * DIM / 4 + 255) / 256, 256>>>(bn_gamma, bn_beta,
                                                           bn_mean, bn_var,
                                                           (float*)d_out);
}